// round 14
// baseline (speedup 1.0000x reference)
#include <cuda_runtime.h>
#include <cuda_fp16.h>
#include <cstdint>

#define N_NODES 50000
#define N_EDGES 600000
#define D 128
#define SCAN_BLK 1024
#define NB ((N_NODES + SCAN_BLK - 1) / SCAN_BLK)   // 49
#define SK 136   // smem row stride in HALVES (conflict-free fragment LDS)

// ---------------------------------------------------------------------------
// Scratch (device globals: allocation-free, graph-capturable)
// ---------------------------------------------------------------------------
__device__ int    g_deg_i[N_NODES];
__device__ int    g_cursor[N_NODES];
__device__ int    g_off[N_NODES];
__device__ int    g_counter;
__device__ int    g_eidx[N_EDGES];      // src index per edge, CSR order
__device__ float  g_norm[N_NODES];
__device__ __half g_hs[N_NODES * D];    // norm-prescaled layer-1 input (fp16)
__device__ __half g_h1[N_NODES * D];    // norm-prescaled relu output (fp16)
__device__ __half g_agg[N_NODES * D];   // aggregate (fp16)

// ---------------------------------------------------------------------------
// CSR build
// ---------------------------------------------------------------------------
__global__ void zero_kernel() {
    int i = blockIdx.x * blockDim.x + threadIdx.x;
    if (i < N_NODES) g_deg_i[i] = 0;
    if (i == 0) g_counter = 0;
}

__global__ void hist_kernel(const int4* __restrict__ dst4) {
    int i = blockIdx.x * blockDim.x + threadIdx.x;
    if (i < N_EDGES / 4) {
        int4 d = __ldg(&dst4[i]);
        atomicAdd(&g_deg_i[d.x], 1);
        atomicAdd(&g_deg_i[d.y], 1);
        atomicAdd(&g_deg_i[d.z], 1);
        atomicAdd(&g_deg_i[d.w], 1);
    }
}

__device__ __forceinline__ int warp_incl_scan(int x, int lane) {
    #pragma unroll
    for (int ofs = 1; ofs < 32; ofs <<= 1) {
        int t = __shfl_up_sync(0xFFFFFFFFu, x, ofs);
        if (lane >= ofs) x += t;
    }
    return x;
}

__global__ __launch_bounds__(SCAN_BLK) void scan_kernel() {
    __shared__ int wsum[32];
    __shared__ int base_s;
    int tid = threadIdx.x, lane = tid & 31, wid = tid >> 5;
    int idx = blockIdx.x * SCAN_BLK + tid;

    int v = (idx < N_NODES) ? g_deg_i[idx] : 0;
    int incl = warp_incl_scan(v, lane);
    if (lane == 31) wsum[wid] = incl;
    __syncthreads();
    if (wid == 0) {
        int s = wsum[lane];
        int si = warp_incl_scan(s, lane);
        wsum[lane] = si - s;
    }
    __syncthreads();
    incl += wsum[wid];
    if (tid == SCAN_BLK - 1) base_s = atomicAdd(&g_counter, incl);
    __syncthreads();

    if (idx < N_NODES) {
        int excl = base_s + incl - v;
        g_off[idx]    = excl;
        g_cursor[idx] = excl;
        g_norm[idx]   = rsqrtf(fmaxf((float)v, 1.0f));
    }
}

// Fill CSR edge list: 2 edges per thread (wider grid -> more atomic chains).
__global__ void fill_kernel(const int2* __restrict__ src2,
                            const int2* __restrict__ dst2) {
    int i = blockIdx.x * blockDim.x + threadIdx.x;
    if (i < N_EDGES / 2) {
        int2 s = __ldg(&src2[i]);
        int2 d = __ldg(&dst2[i]);
        int q0 = atomicAdd(&g_cursor[d.x], 1);
        int q1 = atomicAdd(&g_cursor[d.y], 1);
        g_eidx[q0] = s.x;
        g_eidx[q1] = s.y;
    }
}

// Prescale features by node norm -> fp16 (proven wide-grid kernel).
__global__ void prescale_kernel(const float4* __restrict__ f) {
    int i = blockIdx.x * blockDim.x + threadIdx.x;
    if (i < N_NODES * (D / 4)) {
        float nm = g_norm[i >> 5];
        float4 v = __ldg(&f[i]);
        half2 a = __floats2half2_rn(v.x * nm, v.y * nm);
        half2 b = __floats2half2_rn(v.z * nm, v.w * nm);
        uint2 u;
        u.x = *reinterpret_cast<unsigned*>(&a);
        u.y = *reinterpret_cast<unsigned*>(&b);
        reinterpret_cast<uint2*>(g_hs)[i] = u;
    }
}

// ---------------------------------------------------------------------------
// CSR aggregate: one warp per dst node, HALF-WARP row gathers (LDG.128).
// Lane l: half = l & 15 (owns 8 half-cols), pair = l >> 4 (edge parity).
// Each load step covers 2 edges; unroll 4 steps -> 8 edges in flight.
// Final shfl_xor(16) folds pair accumulators; lanes 0-15 write the row.
// ---------------------------------------------------------------------------
template <bool LAYER1>
__global__ __launch_bounds__(256) void aggregate_kernel() {
    int warp = (blockIdx.x * blockDim.x + threadIdx.x) >> 5;
    int lane = threadIdx.x & 31;
    if (warp >= N_NODES) return;
    const uint4* __restrict__ h4 = reinterpret_cast<const uint4*>(
        LAYER1 ? g_hs : g_h1);   // 16 uint4 per row
    int half = lane & 15;
    int pair = lane >> 4;

    int beg = g_off[warp];
    int end = beg + __ldg(&g_deg_i[warp]);

    float acc[8];
    #pragma unroll
    for (int c = 0; c < 8; c++) acc[c] = 0.f;

    for (int base = beg; base < end; base += 32) {
        int n = end - base;
        if (n > 32) n = 32;
        int idx = 0;
        if (lane < n) idx = __ldg(&g_eidx[base + lane]);  // coalesced

        int j = 0;
        // 8 edges per iteration: 4 LDG.128 per lane, 2 edges per load step
        for (; j + 8 <= n; j += 8) {
            int e0 = __shfl_sync(0xFFFFFFFFu, idx, j + 0 + pair);
            int e1 = __shfl_sync(0xFFFFFFFFu, idx, j + 2 + pair);
            int e2 = __shfl_sync(0xFFFFFFFFu, idx, j + 4 + pair);
            int e3 = __shfl_sync(0xFFFFFFFFu, idx, j + 6 + pair);
            uint4 u0 = __ldg(&h4[e0 * 16 + half]);
            uint4 u1 = __ldg(&h4[e1 * 16 + half]);
            uint4 u2 = __ldg(&h4[e2 * 16 + half]);
            uint4 u3 = __ldg(&h4[e3 * 16 + half]);
            #pragma unroll
            for (int q = 0; q < 4; q++) {
                unsigned w0 = (&u0.x)[q], w1 = (&u1.x)[q];
                unsigned w2 = (&u2.x)[q], w3 = (&u3.x)[q];
                float2 f0 = __half22float2(*reinterpret_cast<half2*>(&w0));
                float2 f1 = __half22float2(*reinterpret_cast<half2*>(&w1));
                float2 f2 = __half22float2(*reinterpret_cast<half2*>(&w2));
                float2 f3 = __half22float2(*reinterpret_cast<half2*>(&w3));
                acc[2 * q + 0] += (f0.x + f1.x) + (f2.x + f3.x);
                acc[2 * q + 1] += (f0.y + f1.y) + (f2.y + f3.y);
            }
        }
        // 2 edges per step
        for (; j + 2 <= n; j += 2) {
            int e0 = __shfl_sync(0xFFFFFFFFu, idx, j + pair);
            uint4 u0 = __ldg(&h4[e0 * 16 + half]);
            #pragma unroll
            for (int q = 0; q < 4; q++) {
                unsigned w0 = (&u0.x)[q];
                float2 f0 = __half22float2(*reinterpret_cast<half2*>(&w0));
                acc[2 * q + 0] += f0.x;
                acc[2 * q + 1] += f0.y;
            }
        }
        // odd tail: pair-0 half-warp only
        if (j < n) {
            int e0 = __shfl_sync(0xFFFFFFFFu, idx, j);
            if (pair == 0) {
                uint4 u0 = __ldg(&h4[e0 * 16 + half]);
                #pragma unroll
                for (int q = 0; q < 4; q++) {
                    unsigned w0 = (&u0.x)[q];
                    float2 f0 = __half22float2(*reinterpret_cast<half2*>(&w0));
                    acc[2 * q + 0] += f0.x;
                    acc[2 * q + 1] += f0.y;
                }
            }
        }
    }

    // Fold pair accumulators
    #pragma unroll
    for (int c = 0; c < 8; c++)
        acc[c] += __shfl_xor_sync(0xFFFFFFFFu, acc[c], 16);

    if (pair == 0) {
        float dn = g_norm[warp];
        uint4 u;
        #pragma unroll
        for (int q = 0; q < 4; q++) {
            half2 hv = __floats2half2_rn(acc[2 * q] * dn, acc[2 * q + 1] * dn);
            (&u.x)[q] = *reinterpret_cast<unsigned*>(&hv);
        }
        reinterpret_cast<uint4*>(g_agg)[warp * 16 + half] = u;
    }
}

// ---------------------------------------------------------------------------
// fp16 MMA m16n8k16 (proven round-13 layout)
// ---------------------------------------------------------------------------
__device__ __forceinline__ void mma_f16(float* d, const unsigned* a,
                                        const unsigned* b) {
    asm("mma.sync.aligned.m16n8k16.row.col.f32.f16.f16.f32 "
        "{%0,%1,%2,%3}, {%4,%5,%6,%7}, {%8,%9}, {%0,%1,%2,%3};"
        : "+f"(d[0]), "+f"(d[1]), "+f"(d[2]), "+f"(d[3])
        : "r"(a[0]), "r"(a[1]), "r"(a[2]), "r"(a[3]), "r"(b[0]), "r"(b[1]));
}

// ---------------------------------------------------------------------------
// Epilogue GEMM on tensor cores (fp16 in, fp32 accum) — proven round-13.
// ---------------------------------------------------------------------------
template <bool LAYER1>
__global__ __launch_bounds__(256) void epilogue_kernel(
    const float* __restrict__ W, const float* __restrict__ bias,
    float* __restrict__ outp) {
    extern __shared__ __half smem_h[];
    __half* sWt = smem_h;            // [128 n][SK]
    __half* sH  = smem_h + D * SK;   // [128 m][SK]

    int tid  = threadIdx.x;
    int lane = tid & 31;
    int warp = tid >> 5;
    int warpM = warp & 3;
    int warpN = warp >> 2;
    int g = lane >> 2;
    int t = lane & 3;
    int row0 = blockIdx.x * 128;

    for (int i = tid; i < D * D / 4; i += 256) {
        int k  = i >> 5;
        int n0 = (i & 31) * 4;
        float4 w = __ldg(&reinterpret_cast<const float4*>(W)[i]);
        sWt[(n0 + 0) * SK + k] = __float2half_rn(w.x);
        sWt[(n0 + 1) * SK + k] = __float2half_rn(w.y);
        sWt[(n0 + 2) * SK + k] = __float2half_rn(w.z);
        sWt[(n0 + 3) * SK + k] = __float2half_rn(w.w);
    }

    for (int i = tid; i < 128 * (D / 4); i += 256) {
        int r  = i >> 5;
        int c4 = i & 31;
        int node = row0 + r;
        uint2 u = make_uint2(0u, 0u);
        if (node < N_NODES)
            u = reinterpret_cast<const uint2*>(g_agg)[node * 32 + c4];
        *reinterpret_cast<uint2*>(&sH[r * SK + c4 * 4]) = u;
    }
    __syncthreads();

    float acc[2][8][4];
    #pragma unroll
    for (int mi = 0; mi < 2; mi++)
        #pragma unroll
        for (int ni = 0; ni < 8; ni++)
            #pragma unroll
            for (int c = 0; c < 4; c++) acc[mi][ni][c] = 0.f;

    #pragma unroll
    for (int kt = 0; kt < 8; kt++) {
        int k0 = kt * 16;
        unsigned a[2][4];
        #pragma unroll
        for (int mi = 0; mi < 2; mi++) {
            int R = warpM * 32 + mi * 16;
            a[mi][0] = *reinterpret_cast<const unsigned*>(&sH[(R + g)     * SK + k0 + 2 * t]);
            a[mi][1] = *reinterpret_cast<const unsigned*>(&sH[(R + g + 8) * SK + k0 + 2 * t]);
            a[mi][2] = *reinterpret_cast<const unsigned*>(&sH[(R + g)     * SK + k0 + 2 * t + 8]);
            a[mi][3] = *reinterpret_cast<const unsigned*>(&sH[(R + g + 8) * SK + k0 + 2 * t + 8]);
        }
        #pragma unroll
        for (int ni = 0; ni < 8; ni++) {
            int C = warpN * 64 + ni * 8;
            unsigned b[2];
            b[0] = *reinterpret_cast<const unsigned*>(&sWt[(C + g) * SK + k0 + 2 * t]);
            b[1] = *reinterpret_cast<const unsigned*>(&sWt[(C + g) * SK + k0 + 2 * t + 8]);
            mma_f16(acc[0][ni], a[0], b);
            mma_f16(acc[1][ni], a[1], b);
        }
    }

    float nmA[2] = {1.f, 1.f}, nmB[2] = {1.f, 1.f};
    if (LAYER1) {
        #pragma unroll
        for (int mi = 0; mi < 2; mi++) {
            int r1 = row0 + warpM * 32 + mi * 16 + g;
            int r2 = r1 + 8;
            nmA[mi] = (r1 < N_NODES) ? g_norm[r1] : 0.f;
            nmB[mi] = (r2 < N_NODES) ? g_norm[r2] : 0.f;
        }
    }

    #pragma unroll
    for (int ni = 0; ni < 8; ni++) {
        int c = warpN * 64 + ni * 8 + 2 * t;
        float2 bb = *reinterpret_cast<const float2*>(&bias[c]);
        #pragma unroll
        for (int mi = 0; mi < 2; mi++) {
            int r1 = row0 + warpM * 32 + mi * 16 + g;
            int r2 = r1 + 8;
            float2 o1 = make_float2(acc[mi][ni][0] + bb.x,
                                    acc[mi][ni][1] + bb.y);
            float2 o2 = make_float2(acc[mi][ni][2] + bb.x,
                                    acc[mi][ni][3] + bb.y);
            if (LAYER1) {
                o1.x = fmaxf(o1.x, 0.f) * nmA[mi];
                o1.y = fmaxf(o1.y, 0.f) * nmA[mi];
                o2.x = fmaxf(o2.x, 0.f) * nmB[mi];
                o2.y = fmaxf(o2.y, 0.f) * nmB[mi];
                if (r1 < N_NODES)
                    *reinterpret_cast<half2*>(&g_h1[r1 * D + c]) =
                        __floats2half2_rn(o1.x, o1.y);
                if (r2 < N_NODES)
                    *reinterpret_cast<half2*>(&g_h1[r2 * D + c]) =
                        __floats2half2_rn(o2.x, o2.y);
            } else {
                if (r1 < N_NODES)
                    *reinterpret_cast<float2*>(&outp[r1 * D + c]) = o1;
                if (r2 < N_NODES)
                    *reinterpret_cast<float2*>(&outp[r2 * D + c]) = o2;
            }
        }
    }
}

// ---------------------------------------------------------------------------
// Launch
// ---------------------------------------------------------------------------
extern "C" void kernel_launch(void* const* d_in, const int* in_sizes, int n_in,
                              void* d_out, int out_size) {
    const float* features = (const float*)d_in[0];
    const int*   src      = (const int*)d_in[1];
    const int*   dst      = (const int*)d_in[2];
    const float* W0       = (const float*)d_in[3];
    const float* b0       = (const float*)d_in[4];
    const float* W1       = (const float*)d_in[5];
    const float* b1       = (const float*)d_in[6];
    float* out = (float*)d_out;

    const int SMEM_EPI = 2 * D * SK * sizeof(__half);  // 69632 B
    cudaFuncSetAttribute(epilogue_kernel<true>,
                         cudaFuncAttributeMaxDynamicSharedMemorySize, SMEM_EPI);
    cudaFuncSetAttribute(epilogue_kernel<false>,
                         cudaFuncAttributeMaxDynamicSharedMemorySize, SMEM_EPI);

    const int nodesBlocks = (N_NODES + 255) / 256;
    const int edge4Blocks = (N_EDGES / 4 + 255) / 256;
    const int edge2Blocks = (N_EDGES / 2 + 255) / 256;
    const int vecBlocks   = (N_NODES * (D / 4) + 255) / 256;
    const int aggBlocks   = (N_NODES + 7) / 8;
    const int epiBlocks   = (N_NODES + 127) / 128;

    // CSR build + prescale (5 launches)
    zero_kernel<<<nodesBlocks, 256>>>();
    hist_kernel<<<edge4Blocks, 256>>>((const int4*)dst);
    scan_kernel<<<NB, SCAN_BLK>>>();
    fill_kernel<<<edge2Blocks, 256>>>((const int2*)src, (const int2*)dst);
    prescale_kernel<<<vecBlocks, 256>>>((const float4*)features);

    // Layer 1
    aggregate_kernel<true><<<aggBlocks, 256>>>();
    epilogue_kernel<true><<<epiBlocks, 256, SMEM_EPI>>>(W0, b0, nullptr);

    // Layer 2
    aggregate_kernel<false><<<aggBlocks, 256>>>();
    epilogue_kernel<false><<<epiBlocks, 256, SMEM_EPI>>>(W1, b1, out);
}

// round 15
// speedup vs baseline: 1.0608x; 1.0608x over previous
#include <cuda_runtime.h>
#include <cuda_fp16.h>
#include <cstdint>

#define N_NODES 50000
#define N_EDGES 600000
#define D 128
#define SCAN_BLK 1024
#define NB ((N_NODES + SCAN_BLK - 1) / SCAN_BLK)   // 49
#define SK 136   // smem row stride in HALVES (conflict-free fragment LDS)

#define FILL_BLOCKS ((N_EDGES / 2 + 255) / 256)            // 1172
#define PRE_BLOCKS  ((N_NODES * (D / 4) + 255) / 256)      // 6250

// ---------------------------------------------------------------------------
// Scratch (device globals: allocation-free, graph-capturable)
// ---------------------------------------------------------------------------
__device__ int    g_deg_i[N_NODES];
__device__ int    g_cursor[N_NODES];
__device__ int    g_off[N_NODES];
__device__ int    g_counter;
__device__ int    g_eidx[N_EDGES];      // src index per edge, CSR order
__device__ float  g_norm[N_NODES];
__device__ __half g_hs[N_NODES * D];    // norm-prescaled layer-1 input (fp16)
__device__ __half g_h1[N_NODES * D];    // norm-prescaled relu output (fp16)
__device__ __half g_agg[N_NODES * D];   // aggregate (fp16)

// ---------------------------------------------------------------------------
// CSR build
// ---------------------------------------------------------------------------
__global__ void zero_kernel() {
    int i = blockIdx.x * blockDim.x + threadIdx.x;
    if (i < N_NODES) g_deg_i[i] = 0;
    if (i == 0) g_counter = 0;
}

__global__ void hist_kernel(const int4* __restrict__ dst4) {
    int i = blockIdx.x * blockDim.x + threadIdx.x;
    if (i < N_EDGES / 4) {
        int4 d = __ldg(&dst4[i]);
        atomicAdd(&g_deg_i[d.x], 1);
        atomicAdd(&g_deg_i[d.y], 1);
        atomicAdd(&g_deg_i[d.z], 1);
        atomicAdd(&g_deg_i[d.w], 1);
    }
}

__device__ __forceinline__ int warp_incl_scan(int x, int lane) {
    #pragma unroll
    for (int ofs = 1; ofs < 32; ofs <<= 1) {
        int t = __shfl_up_sync(0xFFFFFFFFu, x, ofs);
        if (lane >= ofs) x += t;
    }
    return x;
}

__global__ __launch_bounds__(SCAN_BLK) void scan_kernel() {
    __shared__ int wsum[32];
    __shared__ int base_s;
    int tid = threadIdx.x, lane = tid & 31, wid = tid >> 5;
    int idx = blockIdx.x * SCAN_BLK + tid;

    int v = (idx < N_NODES) ? g_deg_i[idx] : 0;
    int incl = warp_incl_scan(v, lane);
    if (lane == 31) wsum[wid] = incl;
    __syncthreads();
    if (wid == 0) {
        int s = wsum[lane];
        int si = warp_incl_scan(s, lane);
        wsum[lane] = si - s;
    }
    __syncthreads();
    incl += wsum[wid];
    if (tid == SCAN_BLK - 1) base_s = atomicAdd(&g_counter, incl);
    __syncthreads();

    if (idx < N_NODES) {
        int excl = base_s + incl - v;
        g_off[idx]    = excl;
        g_cursor[idx] = excl;
        g_norm[idx]   = rsqrtf(fmaxf((float)v, 1.0f));
    }
}

// Fused fill + prescale: both depend only on scan, are independent of each
// other, and have complementary bottlenecks (fill: atomic latency; prescale:
// bandwidth). Blocks [0, FILL_BLOCKS) fill the CSR edge list; the remaining
// blocks prescale the feature rows to fp16.
__global__ void fill_prescale_kernel(const int2* __restrict__ src2,
                                     const int2* __restrict__ dst2,
                                     const float4* __restrict__ f) {
    int b = blockIdx.x;
    if (b < FILL_BLOCKS) {
        int i = b * blockDim.x + threadIdx.x;
        if (i < N_EDGES / 2) {
            int2 s = __ldg(&src2[i]);
            int2 d = __ldg(&dst2[i]);
            int q0 = atomicAdd(&g_cursor[d.x], 1);
            int q1 = atomicAdd(&g_cursor[d.y], 1);
            g_eidx[q0] = s.x;
            g_eidx[q1] = s.y;
        }
    } else {
        int i = (b - FILL_BLOCKS) * blockDim.x + threadIdx.x;
        if (i < N_NODES * (D / 4)) {
            float nm = g_norm[i >> 5];
            float4 v = __ldg(&f[i]);
            half2 a = __floats2half2_rn(v.x * nm, v.y * nm);
            half2 bb = __floats2half2_rn(v.z * nm, v.w * nm);
            uint2 u;
            u.x = *reinterpret_cast<unsigned*>(&a);
            u.y = *reinterpret_cast<unsigned*>(&bb);
            reinterpret_cast<uint2*>(g_hs)[i] = u;
        }
    }
}

// ---------------------------------------------------------------------------
// CSR aggregate (FROZEN round-13 proven shape): one warp per dst node,
// fp16 rows (LDG.64/lane), fp32 accumulation, fp16 output.
// ---------------------------------------------------------------------------
template <bool LAYER1>
__global__ __launch_bounds__(256) void aggregate_kernel() {
    int warp = (blockIdx.x * blockDim.x + threadIdx.x) >> 5;
    int lane = threadIdx.x & 31;
    if (warp >= N_NODES) return;
    const uint2* __restrict__ h = reinterpret_cast<const uint2*>(
        LAYER1 ? g_hs : g_h1);

    int beg = g_off[warp];
    int end = beg + __ldg(&g_deg_i[warp]);

    float4 acc = make_float4(0.f, 0.f, 0.f, 0.f);

    for (int base = beg; base < end; base += 32) {
        int n = end - base;
        if (n > 32) n = 32;
        int idx = 0;
        if (lane < n) idx = __ldg(&g_eidx[base + lane]);
        int j = 0;
        for (; j + 4 <= n; j += 4) {
            int s0 = __shfl_sync(0xFFFFFFFFu, idx, j);
            int s1 = __shfl_sync(0xFFFFFFFFu, idx, j + 1);
            int s2 = __shfl_sync(0xFFFFFFFFu, idx, j + 2);
            int s3 = __shfl_sync(0xFFFFFFFFu, idx, j + 3);
            uint2 u0 = __ldg(&h[s0 * 32 + lane]);
            uint2 u1 = __ldg(&h[s1 * 32 + lane]);
            uint2 u2 = __ldg(&h[s2 * 32 + lane]);
            uint2 u3 = __ldg(&h[s3 * 32 + lane]);
            float2 a0 = __half22float2(*reinterpret_cast<half2*>(&u0.x));
            float2 b0 = __half22float2(*reinterpret_cast<half2*>(&u0.y));
            float2 a1 = __half22float2(*reinterpret_cast<half2*>(&u1.x));
            float2 b1 = __half22float2(*reinterpret_cast<half2*>(&u1.y));
            float2 a2 = __half22float2(*reinterpret_cast<half2*>(&u2.x));
            float2 b2 = __half22float2(*reinterpret_cast<half2*>(&u2.y));
            float2 a3 = __half22float2(*reinterpret_cast<half2*>(&u3.x));
            float2 b3 = __half22float2(*reinterpret_cast<half2*>(&u3.y));
            float tx0 = a0.x + a1.x, tx1 = a2.x + a3.x;
            float ty0 = a0.y + a1.y, ty1 = a2.y + a3.y;
            float tz0 = b0.x + b1.x, tz1 = b2.x + b3.x;
            float tw0 = b0.y + b1.y, tw1 = b2.y + b3.y;
            acc.x += tx0 + tx1;
            acc.y += ty0 + ty1;
            acc.z += tz0 + tz1;
            acc.w += tw0 + tw1;
        }
        for (; j < n; j++) {
            int s0 = __shfl_sync(0xFFFFFFFFu, idx, j);
            uint2 u0 = __ldg(&h[s0 * 32 + lane]);
            float2 a0 = __half22float2(*reinterpret_cast<half2*>(&u0.x));
            float2 b0 = __half22float2(*reinterpret_cast<half2*>(&u0.y));
            acc.x += a0.x; acc.y += a0.y; acc.z += b0.x; acc.w += b0.y;
        }
    }
    float dn = g_norm[warp];
    half2 o1 = __floats2half2_rn(acc.x * dn, acc.y * dn);
    half2 o2 = __floats2half2_rn(acc.z * dn, acc.w * dn);
    uint2 u;
    u.x = *reinterpret_cast<unsigned*>(&o1);
    u.y = *reinterpret_cast<unsigned*>(&o2);
    reinterpret_cast<uint2*>(g_agg)[warp * 32 + lane] = u;
}

// ---------------------------------------------------------------------------
// fp16 MMA m16n8k16 (proven round-13 layout)
// ---------------------------------------------------------------------------
__device__ __forceinline__ void mma_f16(float* d, const unsigned* a,
                                        const unsigned* b) {
    asm("mma.sync.aligned.m16n8k16.row.col.f32.f16.f16.f32 "
        "{%0,%1,%2,%3}, {%4,%5,%6,%7}, {%8,%9}, {%0,%1,%2,%3};"
        : "+f"(d[0]), "+f"(d[1]), "+f"(d[2]), "+f"(d[3])
        : "r"(a[0]), "r"(a[1]), "r"(a[2]), "r"(a[3]), "r"(b[0]), "r"(b[1]));
}

// ---------------------------------------------------------------------------
// Epilogue GEMM on tensor cores (fp16 in, fp32 accum) — proven round-13.
// ---------------------------------------------------------------------------
template <bool LAYER1>
__global__ __launch_bounds__(256) void epilogue_kernel(
    const float* __restrict__ W, const float* __restrict__ bias,
    float* __restrict__ outp) {
    extern __shared__ __half smem_h[];
    __half* sWt = smem_h;            // [128 n][SK]
    __half* sH  = smem_h + D * SK;   // [128 m][SK]

    int tid  = threadIdx.x;
    int lane = tid & 31;
    int warp = tid >> 5;
    int warpM = warp & 3;
    int warpN = warp >> 2;
    int g = lane >> 2;
    int t = lane & 3;
    int row0 = blockIdx.x * 128;

    for (int i = tid; i < D * D / 4; i += 256) {
        int k  = i >> 5;
        int n0 = (i & 31) * 4;
        float4 w = __ldg(&reinterpret_cast<const float4*>(W)[i]);
        sWt[(n0 + 0) * SK + k] = __float2half_rn(w.x);
        sWt[(n0 + 1) * SK + k] = __float2half_rn(w.y);
        sWt[(n0 + 2) * SK + k] = __float2half_rn(w.z);
        sWt[(n0 + 3) * SK + k] = __float2half_rn(w.w);
    }

    for (int i = tid; i < 128 * (D / 4); i += 256) {
        int r  = i >> 5;
        int c4 = i & 31;
        int node = row0 + r;
        uint2 u = make_uint2(0u, 0u);
        if (node < N_NODES)
            u = reinterpret_cast<const uint2*>(g_agg)[node * 32 + c4];
        *reinterpret_cast<uint2*>(&sH[r * SK + c4 * 4]) = u;
    }
    __syncthreads();

    float acc[2][8][4];
    #pragma unroll
    for (int mi = 0; mi < 2; mi++)
        #pragma unroll
        for (int ni = 0; ni < 8; ni++)
            #pragma unroll
            for (int c = 0; c < 4; c++) acc[mi][ni][c] = 0.f;

    #pragma unroll
    for (int kt = 0; kt < 8; kt++) {
        int k0 = kt * 16;
        unsigned a[2][4];
        #pragma unroll
        for (int mi = 0; mi < 2; mi++) {
            int R = warpM * 32 + mi * 16;
            a[mi][0] = *reinterpret_cast<const unsigned*>(&sH[(R + g)     * SK + k0 + 2 * t]);
            a[mi][1] = *reinterpret_cast<const unsigned*>(&sH[(R + g + 8) * SK + k0 + 2 * t]);
            a[mi][2] = *reinterpret_cast<const unsigned*>(&sH[(R + g)     * SK + k0 + 2 * t + 8]);
            a[mi][3] = *reinterpret_cast<const unsigned*>(&sH[(R + g + 8) * SK + k0 + 2 * t + 8]);
        }
        #pragma unroll
        for (int ni = 0; ni < 8; ni++) {
            int C = warpN * 64 + ni * 8;
            unsigned b[2];
            b[0] = *reinterpret_cast<const unsigned*>(&sWt[(C + g) * SK + k0 + 2 * t]);
            b[1] = *reinterpret_cast<const unsigned*>(&sWt[(C + g) * SK + k0 + 2 * t + 8]);
            mma_f16(acc[0][ni], a[0], b);
            mma_f16(acc[1][ni], a[1], b);
        }
    }

    float nmA[2] = {1.f, 1.f}, nmB[2] = {1.f, 1.f};
    if (LAYER1) {
        #pragma unroll
        for (int mi = 0; mi < 2; mi++) {
            int r1 = row0 + warpM * 32 + mi * 16 + g;
            int r2 = r1 + 8;
            nmA[mi] = (r1 < N_NODES) ? g_norm[r1] : 0.f;
            nmB[mi] = (r2 < N_NODES) ? g_norm[r2] : 0.f;
        }
    }

    #pragma unroll
    for (int ni = 0; ni < 8; ni++) {
        int c = warpN * 64 + ni * 8 + 2 * t;
        float2 bb = *reinterpret_cast<const float2*>(&bias[c]);
        #pragma unroll
        for (int mi = 0; mi < 2; mi++) {
            int r1 = row0 + warpM * 32 + mi * 16 + g;
            int r2 = r1 + 8;
            float2 o1 = make_float2(acc[mi][ni][0] + bb.x,
                                    acc[mi][ni][1] + bb.y);
            float2 o2 = make_float2(acc[mi][ni][2] + bb.x,
                                    acc[mi][ni][3] + bb.y);
            if (LAYER1) {
                o1.x = fmaxf(o1.x, 0.f) * nmA[mi];
                o1.y = fmaxf(o1.y, 0.f) * nmA[mi];
                o2.x = fmaxf(o2.x, 0.f) * nmB[mi];
                o2.y = fmaxf(o2.y, 0.f) * nmB[mi];
                if (r1 < N_NODES)
                    *reinterpret_cast<half2*>(&g_h1[r1 * D + c]) =
                        __floats2half2_rn(o1.x, o1.y);
                if (r2 < N_NODES)
                    *reinterpret_cast<half2*>(&g_h1[r2 * D + c]) =
                        __floats2half2_rn(o2.x, o2.y);
            } else {
                if (r1 < N_NODES)
                    *reinterpret_cast<float2*>(&outp[r1 * D + c]) = o1;
                if (r2 < N_NODES)
                    *reinterpret_cast<float2*>(&outp[r2 * D + c]) = o2;
            }
        }
    }
}

// ---------------------------------------------------------------------------
// Launch
// ---------------------------------------------------------------------------
extern "C" void kernel_launch(void* const* d_in, const int* in_sizes, int n_in,
                              void* d_out, int out_size) {
    const float* features = (const float*)d_in[0];
    const int*   src      = (const int*)d_in[1];
    const int*   dst      = (const int*)d_in[2];
    const float* W0       = (const float*)d_in[3];
    const float* b0       = (const float*)d_in[4];
    const float* W1       = (const float*)d_in[5];
    const float* b1       = (const float*)d_in[6];
    float* out = (float*)d_out;

    const int SMEM_EPI = 2 * D * SK * sizeof(__half);  // 69632 B
    cudaFuncSetAttribute(epilogue_kernel<true>,
                         cudaFuncAttributeMaxDynamicSharedMemorySize, SMEM_EPI);
    cudaFuncSetAttribute(epilogue_kernel<false>,
                         cudaFuncAttributeMaxDynamicSharedMemorySize, SMEM_EPI);

    const int nodesBlocks = (N_NODES + 255) / 256;
    const int edge4Blocks = (N_EDGES / 4 + 255) / 256;
    const int aggBlocks   = (N_NODES + 7) / 8;
    const int epiBlocks   = (N_NODES + 127) / 128;

    // CSR build + prescale (4 launches)
    zero_kernel<<<nodesBlocks, 256>>>();
    hist_kernel<<<edge4Blocks, 256>>>((const int4*)dst);
    scan_kernel<<<NB, SCAN_BLK>>>();
    fill_prescale_kernel<<<FILL_BLOCKS + PRE_BLOCKS, 256>>>(
        (const int2*)src, (const int2*)dst, (const float4*)features);

    // Layer 1
    aggregate_kernel<true><<<aggBlocks, 256>>>();
    epilogue_kernel<true><<<epiBlocks, 256, SMEM_EPI>>>(W0, b0, nullptr);

    // Layer 2
    aggregate_kernel<false><<<aggBlocks, 256>>>();
    epilogue_kernel<false><<<epiBlocks, 256, SMEM_EPI>>>(W1, b1, out);
}

// round 16
// speedup vs baseline: 1.0750x; 1.0134x over previous
#include <cuda_runtime.h>
#include <cuda_fp16.h>
#include <cstdint>

#define N_NODES 50000
#define N_EDGES 600000
#define D 128
#define SCAN_BLK 1024
#define NB ((N_NODES + SCAN_BLK - 1) / SCAN_BLK)   // 49
#define SK 136   // smem row stride in HALVES (conflict-free fragment LDS)

#define FILL_BLOCKS ((N_EDGES / 2 + 255) / 256)            // 1172
#define PRE_BLOCKS  ((N_NODES * (D / 4) + 255) / 256)      // 6250

// ---------------------------------------------------------------------------
// Scratch (device globals: allocation-free, graph-capturable)
// NOTE: g_deg_i / g_counter are zero at module load (static init) and are
// re-zeroed at the END of each kernel_launch (inside epilogue<false>), so no
// standalone zero kernel is needed. Invariant: every launch leaves them zero.
// ---------------------------------------------------------------------------
__device__ int    g_deg_i[N_NODES];
__device__ int    g_cursor[N_NODES];
__device__ int    g_off[N_NODES];
__device__ int    g_counter;
__device__ int    g_eidx[N_EDGES];      // src index per edge, CSR order
__device__ float  g_norm[N_NODES];
__device__ __half g_hs[N_NODES * D];    // norm-prescaled layer-1 input (fp16)
__device__ __half g_h1[N_NODES * D];    // norm-prescaled relu output (fp16)
__device__ __half g_agg[N_NODES * D];   // aggregate (fp16)

// ---------------------------------------------------------------------------
// CSR build
// ---------------------------------------------------------------------------
__global__ void hist_kernel(const int4* __restrict__ dst4) {
    int i = blockIdx.x * blockDim.x + threadIdx.x;
    if (i < N_EDGES / 4) {
        int4 d = __ldg(&dst4[i]);
        atomicAdd(&g_deg_i[d.x], 1);
        atomicAdd(&g_deg_i[d.y], 1);
        atomicAdd(&g_deg_i[d.z], 1);
        atomicAdd(&g_deg_i[d.w], 1);
    }
}

__device__ __forceinline__ int warp_incl_scan(int x, int lane) {
    #pragma unroll
    for (int ofs = 1; ofs < 32; ofs <<= 1) {
        int t = __shfl_up_sync(0xFFFFFFFFu, x, ofs);
        if (lane >= ofs) x += t;
    }
    return x;
}

__global__ __launch_bounds__(SCAN_BLK) void scan_kernel() {
    __shared__ int wsum[32];
    __shared__ int base_s;
    int tid = threadIdx.x, lane = tid & 31, wid = tid >> 5;
    int idx = blockIdx.x * SCAN_BLK + tid;

    int v = (idx < N_NODES) ? g_deg_i[idx] : 0;
    int incl = warp_incl_scan(v, lane);
    if (lane == 31) wsum[wid] = incl;
    __syncthreads();
    if (wid == 0) {
        int s = wsum[lane];
        int si = warp_incl_scan(s, lane);
        wsum[lane] = si - s;
    }
    __syncthreads();
    incl += wsum[wid];
    if (tid == SCAN_BLK - 1) base_s = atomicAdd(&g_counter, incl);
    __syncthreads();

    if (idx < N_NODES) {
        int excl = base_s + incl - v;
        g_off[idx]    = excl;
        g_cursor[idx] = excl;
        g_norm[idx]   = rsqrtf(fmaxf((float)v, 1.0f));
    }
}

// Fused fill + prescale (proven round-15): blocks [0, FILL_BLOCKS) fill the
// CSR edge list; remaining blocks prescale feature rows to fp16.
__global__ void fill_prescale_kernel(const int2* __restrict__ src2,
                                     const int2* __restrict__ dst2,
                                     const float4* __restrict__ f) {
    int b = blockIdx.x;
    if (b < FILL_BLOCKS) {
        int i = b * blockDim.x + threadIdx.x;
        if (i < N_EDGES / 2) {
            int2 s = __ldg(&src2[i]);
            int2 d = __ldg(&dst2[i]);
            int q0 = atomicAdd(&g_cursor[d.x], 1);
            int q1 = atomicAdd(&g_cursor[d.y], 1);
            g_eidx[q0] = s.x;
            g_eidx[q1] = s.y;
        }
    } else {
        int i = (b - FILL_BLOCKS) * blockDim.x + threadIdx.x;
        if (i < N_NODES * (D / 4)) {
            float nm = g_norm[i >> 5];
            float4 v = __ldg(&f[i]);
            half2 a = __floats2half2_rn(v.x * nm, v.y * nm);
            half2 bb = __floats2half2_rn(v.z * nm, v.w * nm);
            uint2 u;
            u.x = *reinterpret_cast<unsigned*>(&a);
            u.y = *reinterpret_cast<unsigned*>(&bb);
            reinterpret_cast<uint2*>(g_hs)[i] = u;
        }
    }
}

// ---------------------------------------------------------------------------
// CSR aggregate (FROZEN round-13 proven shape): one warp per dst node,
// fp16 rows (LDG.64/lane), fp32 accumulation, fp16 output.
// ---------------------------------------------------------------------------
template <bool LAYER1>
__global__ __launch_bounds__(256) void aggregate_kernel() {
    int warp = (blockIdx.x * blockDim.x + threadIdx.x) >> 5;
    int lane = threadIdx.x & 31;
    if (warp >= N_NODES) return;
    const uint2* __restrict__ h = reinterpret_cast<const uint2*>(
        LAYER1 ? g_hs : g_h1);

    int beg = g_off[warp];
    int end = beg + __ldg(&g_deg_i[warp]);

    float4 acc = make_float4(0.f, 0.f, 0.f, 0.f);

    for (int base = beg; base < end; base += 32) {
        int n = end - base;
        if (n > 32) n = 32;
        int idx = 0;
        if (lane < n) idx = __ldg(&g_eidx[base + lane]);
        int j = 0;
        for (; j + 4 <= n; j += 4) {
            int s0 = __shfl_sync(0xFFFFFFFFu, idx, j);
            int s1 = __shfl_sync(0xFFFFFFFFu, idx, j + 1);
            int s2 = __shfl_sync(0xFFFFFFFFu, idx, j + 2);
            int s3 = __shfl_sync(0xFFFFFFFFu, idx, j + 3);
            uint2 u0 = __ldg(&h[s0 * 32 + lane]);
            uint2 u1 = __ldg(&h[s1 * 32 + lane]);
            uint2 u2 = __ldg(&h[s2 * 32 + lane]);
            uint2 u3 = __ldg(&h[s3 * 32 + lane]);
            float2 a0 = __half22float2(*reinterpret_cast<half2*>(&u0.x));
            float2 b0 = __half22float2(*reinterpret_cast<half2*>(&u0.y));
            float2 a1 = __half22float2(*reinterpret_cast<half2*>(&u1.x));
            float2 b1 = __half22float2(*reinterpret_cast<half2*>(&u1.y));
            float2 a2 = __half22float2(*reinterpret_cast<half2*>(&u2.x));
            float2 b2 = __half22float2(*reinterpret_cast<half2*>(&u2.y));
            float2 a3 = __half22float2(*reinterpret_cast<half2*>(&u3.x));
            float2 b3 = __half22float2(*reinterpret_cast<half2*>(&u3.y));
            float tx0 = a0.x + a1.x, tx1 = a2.x + a3.x;
            float ty0 = a0.y + a1.y, ty1 = a2.y + a3.y;
            float tz0 = b0.x + b1.x, tz1 = b2.x + b3.x;
            float tw0 = b0.y + b1.y, tw1 = b2.y + b3.y;
            acc.x += tx0 + tx1;
            acc.y += ty0 + ty1;
            acc.z += tz0 + tz1;
            acc.w += tw0 + tw1;
        }
        for (; j < n; j++) {
            int s0 = __shfl_sync(0xFFFFFFFFu, idx, j);
            uint2 u0 = __ldg(&h[s0 * 32 + lane]);
            float2 a0 = __half22float2(*reinterpret_cast<half2*>(&u0.x));
            float2 b0 = __half22float2(*reinterpret_cast<half2*>(&u0.y));
            acc.x += a0.x; acc.y += a0.y; acc.z += b0.x; acc.w += b0.y;
        }
    }
    float dn = g_norm[warp];
    half2 o1 = __floats2half2_rn(acc.x * dn, acc.y * dn);
    half2 o2 = __floats2half2_rn(acc.z * dn, acc.w * dn);
    uint2 u;
    u.x = *reinterpret_cast<unsigned*>(&o1);
    u.y = *reinterpret_cast<unsigned*>(&o2);
    reinterpret_cast<uint2*>(g_agg)[warp * 32 + lane] = u;
}

// ---------------------------------------------------------------------------
// fp16 MMA m16n8k16 (proven round-13 layout)
// ---------------------------------------------------------------------------
__device__ __forceinline__ void mma_f16(float* d, const unsigned* a,
                                        const unsigned* b) {
    asm("mma.sync.aligned.m16n8k16.row.col.f32.f16.f16.f32 "
        "{%0,%1,%2,%3}, {%4,%5,%6,%7}, {%8,%9}, {%0,%1,%2,%3};"
        : "+f"(d[0]), "+f"(d[1]), "+f"(d[2]), "+f"(d[3])
        : "r"(a[0]), "r"(a[1]), "r"(a[2]), "r"(a[3]), "r"(b[0]), "r"(b[1]));
}

// ---------------------------------------------------------------------------
// Epilogue GEMM on tensor cores (fp16 in, fp32 accum) — proven round-13.
// LAYER2 additionally resets g_deg_i / g_counter for the next replay
// (it never reads them; runs after everything that does).
// ---------------------------------------------------------------------------
template <bool LAYER1>
__global__ __launch_bounds__(256) void epilogue_kernel(
    const float* __restrict__ W, const float* __restrict__ bias,
    float* __restrict__ outp) {
    extern __shared__ __half smem_h[];
    __half* sWt = smem_h;            // [128 n][SK]
    __half* sH  = smem_h + D * SK;   // [128 m][SK]

    int tid  = threadIdx.x;
    int lane = tid & 31;
    int warp = tid >> 5;
    int warpM = warp & 3;
    int warpN = warp >> 2;
    int g = lane >> 2;
    int t = lane & 3;
    int row0 = blockIdx.x * 128;

    for (int i = tid; i < D * D / 4; i += 256) {
        int k  = i >> 5;
        int n0 = (i & 31) * 4;
        float4 w = __ldg(&reinterpret_cast<const float4*>(W)[i]);
        sWt[(n0 + 0) * SK + k] = __float2half_rn(w.x);
        sWt[(n0 + 1) * SK + k] = __float2half_rn(w.y);
        sWt[(n0 + 2) * SK + k] = __float2half_rn(w.z);
        sWt[(n0 + 3) * SK + k] = __float2half_rn(w.w);
    }

    for (int i = tid; i < 128 * (D / 4); i += 256) {
        int r  = i >> 5;
        int c4 = i & 31;
        int node = row0 + r;
        uint2 u = make_uint2(0u, 0u);
        if (node < N_NODES)
            u = reinterpret_cast<const uint2*>(g_agg)[node * 32 + c4];
        *reinterpret_cast<uint2*>(&sH[r * SK + c4 * 4]) = u;
    }

    // LAYER2: reset per-replay counters (not read by this kernel).
    if (!LAYER1) {
        if (tid < 128) {
            int node = row0 + tid;
            if (node < N_NODES) g_deg_i[node] = 0;
        }
        if (blockIdx.x == 0 && tid == 128) g_counter = 0;
    }
    __syncthreads();

    float acc[2][8][4];
    #pragma unroll
    for (int mi = 0; mi < 2; mi++)
        #pragma unroll
        for (int ni = 0; ni < 8; ni++)
            #pragma unroll
            for (int c = 0; c < 4; c++) acc[mi][ni][c] = 0.f;

    #pragma unroll
    for (int kt = 0; kt < 8; kt++) {
        int k0 = kt * 16;
        unsigned a[2][4];
        #pragma unroll
        for (int mi = 0; mi < 2; mi++) {
            int R = warpM * 32 + mi * 16;
            a[mi][0] = *reinterpret_cast<const unsigned*>(&sH[(R + g)     * SK + k0 + 2 * t]);
            a[mi][1] = *reinterpret_cast<const unsigned*>(&sH[(R + g + 8) * SK + k0 + 2 * t]);
            a[mi][2] = *reinterpret_cast<const unsigned*>(&sH[(R + g)     * SK + k0 + 2 * t + 8]);
            a[mi][3] = *reinterpret_cast<const unsigned*>(&sH[(R + g + 8) * SK + k0 + 2 * t + 8]);
        }
        #pragma unroll
        for (int ni = 0; ni < 8; ni++) {
            int C = warpN * 64 + ni * 8;
            unsigned b[2];
            b[0] = *reinterpret_cast<const unsigned*>(&sWt[(C + g) * SK + k0 + 2 * t]);
            b[1] = *reinterpret_cast<const unsigned*>(&sWt[(C + g) * SK + k0 + 2 * t + 8]);
            mma_f16(acc[0][ni], a[0], b);
            mma_f16(acc[1][ni], a[1], b);
        }
    }

    float nmA[2] = {1.f, 1.f}, nmB[2] = {1.f, 1.f};
    if (LAYER1) {
        #pragma unroll
        for (int mi = 0; mi < 2; mi++) {
            int r1 = row0 + warpM * 32 + mi * 16 + g;
            int r2 = r1 + 8;
            nmA[mi] = (r1 < N_NODES) ? g_norm[r1] : 0.f;
            nmB[mi] = (r2 < N_NODES) ? g_norm[r2] : 0.f;
        }
    }

    #pragma unroll
    for (int ni = 0; ni < 8; ni++) {
        int c = warpN * 64 + ni * 8 + 2 * t;
        float2 bb = *reinterpret_cast<const float2*>(&bias[c]);
        #pragma unroll
        for (int mi = 0; mi < 2; mi++) {
            int r1 = row0 + warpM * 32 + mi * 16 + g;
            int r2 = r1 + 8;
            float2 o1 = make_float2(acc[mi][ni][0] + bb.x,
                                    acc[mi][ni][1] + bb.y);
            float2 o2 = make_float2(acc[mi][ni][2] + bb.x,
                                    acc[mi][ni][3] + bb.y);
            if (LAYER1) {
                o1.x = fmaxf(o1.x, 0.f) * nmA[mi];
                o1.y = fmaxf(o1.y, 0.f) * nmA[mi];
                o2.x = fmaxf(o2.x, 0.f) * nmB[mi];
                o2.y = fmaxf(o2.y, 0.f) * nmB[mi];
                if (r1 < N_NODES)
                    *reinterpret_cast<half2*>(&g_h1[r1 * D + c]) =
                        __floats2half2_rn(o1.x, o1.y);
                if (r2 < N_NODES)
                    *reinterpret_cast<half2*>(&g_h1[r2 * D + c]) =
                        __floats2half2_rn(o2.x, o2.y);
            } else {
                if (r1 < N_NODES)
                    *reinterpret_cast<float2*>(&outp[r1 * D + c]) = o1;
                if (r2 < N_NODES)
                    *reinterpret_cast<float2*>(&outp[r2 * D + c]) = o2;
            }
        }
    }
}

// ---------------------------------------------------------------------------
// Launch
// ---------------------------------------------------------------------------
extern "C" void kernel_launch(void* const* d_in, const int* in_sizes, int n_in,
                              void* d_out, int out_size) {
    const float* features = (const float*)d_in[0];
    const int*   src      = (const int*)d_in[1];
    const int*   dst      = (const int*)d_in[2];
    const float* W0       = (const float*)d_in[3];
    const float* b0       = (const float*)d_in[4];
    const float* W1       = (const float*)d_in[5];
    const float* b1       = (const float*)d_in[6];
    float* out = (float*)d_out;

    const int SMEM_EPI = 2 * D * SK * sizeof(__half);  // 69632 B
    cudaFuncSetAttribute(epilogue_kernel<true>,
                         cudaFuncAttributeMaxDynamicSharedMemorySize, SMEM_EPI);
    cudaFuncSetAttribute(epilogue_kernel<false>,
                         cudaFuncAttributeMaxDynamicSharedMemorySize, SMEM_EPI);

    const int edge4Blocks = (N_EDGES / 4 + 255) / 256;
    const int aggBlocks   = (N_NODES + 7) / 8;
    const int epiBlocks   = (N_NODES + 127) / 128;

    // CSR build + prescale (3 launches; deg/counter pre-zeroed by invariant)
    hist_kernel<<<edge4Blocks, 256>>>((const int4*)dst);
    scan_kernel<<<NB, SCAN_BLK>>>();
    fill_prescale_kernel<<<FILL_BLOCKS + PRE_BLOCKS, 256>>>(
        (const int2*)src, (const int2*)dst, (const float4*)features);

    // Layer 1
    aggregate_kernel<true><<<aggBlocks, 256>>>();
    epilogue_kernel<true><<<epiBlocks, 256, SMEM_EPI>>>(W0, b0, nullptr);

    // Layer 2 (epilogue also resets deg/counter for the next replay)
    aggregate_kernel<false><<<aggBlocks, 256>>>();
    epilogue_kernel<false><<<epiBlocks, 256, SMEM_EPI>>>(W1, b1, out);
}

// round 17
// speedup vs baseline: 1.0950x; 1.0186x over previous
#include <cuda_runtime.h>
#include <cuda_fp16.h>
#include <cstdint>

#define N_NODES 50000
#define N_EDGES 600000
#define D 128
#define SCAN_BLK 1024
#define NB ((N_NODES + SCAN_BLK - 1) / SCAN_BLK)   // 49
#define SK 136   // smem row stride in HALVES (conflict-free fragment LDS)

#define FILL_BLOCKS ((N_EDGES / 2 + 255) / 256)            // 1172
#define PRE_BLOCKS  ((N_NODES * (D / 4) + 255) / 256)      // 6250

// ---------------------------------------------------------------------------
// Scratch (device globals: allocation-free, graph-capturable)
// g_deg_i / g_counter: zero at module load; re-zeroed at END of each launch
// (inside epilogue<false>) -> no standalone zero kernel.
// ---------------------------------------------------------------------------
__device__ int    g_deg_i[N_NODES];
__device__ int    g_cursor[N_NODES];
__device__ int    g_off[N_NODES];
__device__ int    g_counter;
__device__ int    g_eidx[N_EDGES];      // src index per edge, CSR order
__device__ float  g_norm[N_NODES];
__device__ __half g_hs[N_NODES * D];    // norm-prescaled layer-1 input (fp16)
__device__ __half g_h1[N_NODES * D];    // norm-prescaled relu output (fp16)
__device__ __half g_agg[N_NODES * D];   // aggregate (fp16)

// ---------------------------------------------------------------------------
// CSR build (frozen)
// ---------------------------------------------------------------------------
__global__ void hist_kernel(const int4* __restrict__ dst4) {
    int i = blockIdx.x * blockDim.x + threadIdx.x;
    if (i < N_EDGES / 4) {
        int4 d = __ldg(&dst4[i]);
        atomicAdd(&g_deg_i[d.x], 1);
        atomicAdd(&g_deg_i[d.y], 1);
        atomicAdd(&g_deg_i[d.z], 1);
        atomicAdd(&g_deg_i[d.w], 1);
    }
}

__device__ __forceinline__ int warp_incl_scan(int x, int lane) {
    #pragma unroll
    for (int ofs = 1; ofs < 32; ofs <<= 1) {
        int t = __shfl_up_sync(0xFFFFFFFFu, x, ofs);
        if (lane >= ofs) x += t;
    }
    return x;
}

__global__ __launch_bounds__(SCAN_BLK) void scan_kernel() {
    __shared__ int wsum[32];
    __shared__ int base_s;
    int tid = threadIdx.x, lane = tid & 31, wid = tid >> 5;
    int idx = blockIdx.x * SCAN_BLK + tid;

    int v = (idx < N_NODES) ? g_deg_i[idx] : 0;
    int incl = warp_incl_scan(v, lane);
    if (lane == 31) wsum[wid] = incl;
    __syncthreads();
    if (wid == 0) {
        int s = wsum[lane];
        int si = warp_incl_scan(s, lane);
        wsum[lane] = si - s;
    }
    __syncthreads();
    incl += wsum[wid];
    if (tid == SCAN_BLK - 1) base_s = atomicAdd(&g_counter, incl);
    __syncthreads();

    if (idx < N_NODES) {
        int excl = base_s + incl - v;
        g_off[idx]    = excl;
        g_cursor[idx] = excl;
        g_norm[idx]   = rsqrtf(fmaxf((float)v, 1.0f));
    }
}

// Fused fill + prescale (frozen round-15)
__global__ void fill_prescale_kernel(const int2* __restrict__ src2,
                                     const int2* __restrict__ dst2,
                                     const float4* __restrict__ f) {
    int b = blockIdx.x;
    if (b < FILL_BLOCKS) {
        int i = b * blockDim.x + threadIdx.x;
        if (i < N_EDGES / 2) {
            int2 s = __ldg(&src2[i]);
            int2 d = __ldg(&dst2[i]);
            int q0 = atomicAdd(&g_cursor[d.x], 1);
            int q1 = atomicAdd(&g_cursor[d.y], 1);
            g_eidx[q0] = s.x;
            g_eidx[q1] = s.y;
        }
    } else {
        int i = (b - FILL_BLOCKS) * blockDim.x + threadIdx.x;
        if (i < N_NODES * (D / 4)) {
            float nm = g_norm[i >> 5];
            float4 v = __ldg(&f[i]);
            half2 a = __floats2half2_rn(v.x * nm, v.y * nm);
            half2 bb = __floats2half2_rn(v.z * nm, v.w * nm);
            uint2 u;
            u.x = *reinterpret_cast<unsigned*>(&a);
            u.y = *reinterpret_cast<unsigned*>(&bb);
            reinterpret_cast<uint2*>(g_hs)[i] = u;
        }
    }
}

// ---------------------------------------------------------------------------
// CSR aggregate: memory pattern frozen (warp/node, LDG.64/lane, unroll-4).
// NEW: one-level pairwise HADD2 reduction (4 HADD2 + 8 F2F + 8 FADD per 4
// edges vs 16 F2F + 24 FADD before) — kernel is issue-bound per ncu.
// ---------------------------------------------------------------------------
template <bool LAYER1>
__global__ __launch_bounds__(256) void aggregate_kernel() {
    int warp = (blockIdx.x * blockDim.x + threadIdx.x) >> 5;
    int lane = threadIdx.x & 31;
    if (warp >= N_NODES) return;
    const uint2* __restrict__ h = reinterpret_cast<const uint2*>(
        LAYER1 ? g_hs : g_h1);

    int beg = g_off[warp];
    int end = beg + __ldg(&g_deg_i[warp]);

    float4 acc = make_float4(0.f, 0.f, 0.f, 0.f);

    for (int base = beg; base < end; base += 32) {
        int n = end - base;
        if (n > 32) n = 32;
        int idx = 0;
        if (lane < n) idx = __ldg(&g_eidx[base + lane]);
        int j = 0;
        for (; j + 4 <= n; j += 4) {
            int s0 = __shfl_sync(0xFFFFFFFFu, idx, j);
            int s1 = __shfl_sync(0xFFFFFFFFu, idx, j + 1);
            int s2 = __shfl_sync(0xFFFFFFFFu, idx, j + 2);
            int s3 = __shfl_sync(0xFFFFFFFFu, idx, j + 3);
            uint2 u0 = __ldg(&h[s0 * 32 + lane]);
            uint2 u1 = __ldg(&h[s1 * 32 + lane]);
            uint2 u2 = __ldg(&h[s2 * 32 + lane]);
            uint2 u3 = __ldg(&h[s3 * 32 + lane]);
            // one-level fp16 pairwise add (4x HADD2)
            half2 p0x = __hadd2(*reinterpret_cast<half2*>(&u0.x),
                                *reinterpret_cast<half2*>(&u1.x));
            half2 p0y = __hadd2(*reinterpret_cast<half2*>(&u0.y),
                                *reinterpret_cast<half2*>(&u1.y));
            half2 p1x = __hadd2(*reinterpret_cast<half2*>(&u2.x),
                                *reinterpret_cast<half2*>(&u3.x));
            half2 p1y = __hadd2(*reinterpret_cast<half2*>(&u2.y),
                                *reinterpret_cast<half2*>(&u3.y));
            float2 f0 = __half22float2(p0x);
            float2 f1 = __half22float2(p0y);
            float2 f2 = __half22float2(p1x);
            float2 f3 = __half22float2(p1y);
            acc.x += f0.x + f2.x;
            acc.y += f0.y + f2.y;
            acc.z += f1.x + f3.x;
            acc.w += f1.y + f3.y;
        }
        if (j + 2 <= n) {
            int s0 = __shfl_sync(0xFFFFFFFFu, idx, j);
            int s1 = __shfl_sync(0xFFFFFFFFu, idx, j + 1);
            uint2 u0 = __ldg(&h[s0 * 32 + lane]);
            uint2 u1 = __ldg(&h[s1 * 32 + lane]);
            half2 p0x = __hadd2(*reinterpret_cast<half2*>(&u0.x),
                                *reinterpret_cast<half2*>(&u1.x));
            half2 p0y = __hadd2(*reinterpret_cast<half2*>(&u0.y),
                                *reinterpret_cast<half2*>(&u1.y));
            float2 f0 = __half22float2(p0x);
            float2 f1 = __half22float2(p0y);
            acc.x += f0.x; acc.y += f0.y; acc.z += f1.x; acc.w += f1.y;
            j += 2;
        }
        if (j < n) {
            int s0 = __shfl_sync(0xFFFFFFFFu, idx, j);
            uint2 u0 = __ldg(&h[s0 * 32 + lane]);
            float2 a0 = __half22float2(*reinterpret_cast<half2*>(&u0.x));
            float2 b0 = __half22float2(*reinterpret_cast<half2*>(&u0.y));
            acc.x += a0.x; acc.y += a0.y; acc.z += b0.x; acc.w += b0.y;
        }
    }
    float dn = g_norm[warp];
    half2 o1 = __floats2half2_rn(acc.x * dn, acc.y * dn);
    half2 o2 = __floats2half2_rn(acc.z * dn, acc.w * dn);
    uint2 u;
    u.x = *reinterpret_cast<unsigned*>(&o1);
    u.y = *reinterpret_cast<unsigned*>(&o2);
    reinterpret_cast<uint2*>(g_agg)[warp * 32 + lane] = u;
}

// ---------------------------------------------------------------------------
// fp16 MMA m16n8k16 (frozen round-13 layout)
// ---------------------------------------------------------------------------
__device__ __forceinline__ void mma_f16(float* d, const unsigned* a,
                                        const unsigned* b) {
    asm("mma.sync.aligned.m16n8k16.row.col.f32.f16.f16.f32 "
        "{%0,%1,%2,%3}, {%4,%5,%6,%7}, {%8,%9}, {%0,%1,%2,%3};"
        : "+f"(d[0]), "+f"(d[1]), "+f"(d[2]), "+f"(d[3])
        : "r"(a[0]), "r"(a[1]), "r"(a[2]), "r"(a[3]), "r"(b[0]), "r"(b[1]));
}

// ---------------------------------------------------------------------------
// Epilogue GEMM on tensor cores (frozen round-13/16; LAYER2 resets counters)
// ---------------------------------------------------------------------------
template <bool LAYER1>
__global__ __launch_bounds__(256) void epilogue_kernel(
    const float* __restrict__ W, const float* __restrict__ bias,
    float* __restrict__ outp) {
    extern __shared__ __half smem_h[];
    __half* sWt = smem_h;            // [128 n][SK]
    __half* sH  = smem_h + D * SK;   // [128 m][SK]

    int tid  = threadIdx.x;
    int lane = tid & 31;
    int warp = tid >> 5;
    int warpM = warp & 3;
    int warpN = warp >> 2;
    int g = lane >> 2;
    int t = lane & 3;
    int row0 = blockIdx.x * 128;

    for (int i = tid; i < D * D / 4; i += 256) {
        int k  = i >> 5;
        int n0 = (i & 31) * 4;
        float4 w = __ldg(&reinterpret_cast<const float4*>(W)[i]);
        sWt[(n0 + 0) * SK + k] = __float2half_rn(w.x);
        sWt[(n0 + 1) * SK + k] = __float2half_rn(w.y);
        sWt[(n0 + 2) * SK + k] = __float2half_rn(w.z);
        sWt[(n0 + 3) * SK + k] = __float2half_rn(w.w);
    }

    for (int i = tid; i < 128 * (D / 4); i += 256) {
        int r  = i >> 5;
        int c4 = i & 31;
        int node = row0 + r;
        uint2 u = make_uint2(0u, 0u);
        if (node < N_NODES)
            u = reinterpret_cast<const uint2*>(g_agg)[node * 32 + c4];
        *reinterpret_cast<uint2*>(&sH[r * SK + c4 * 4]) = u;
    }

    // LAYER2: reset per-replay counters (not read by this kernel).
    if (!LAYER1) {
        if (tid < 128) {
            int node = row0 + tid;
            if (node < N_NODES) g_deg_i[node] = 0;
        }
        if (blockIdx.x == 0 && tid == 128) g_counter = 0;
    }
    __syncthreads();

    float acc[2][8][4];
    #pragma unroll
    for (int mi = 0; mi < 2; mi++)
        #pragma unroll
        for (int ni = 0; ni < 8; ni++)
            #pragma unroll
            for (int c = 0; c < 4; c++) acc[mi][ni][c] = 0.f;

    #pragma unroll
    for (int kt = 0; kt < 8; kt++) {
        int k0 = kt * 16;
        unsigned a[2][4];
        #pragma unroll
        for (int mi = 0; mi < 2; mi++) {
            int R = warpM * 32 + mi * 16;
            a[mi][0] = *reinterpret_cast<const unsigned*>(&sH[(R + g)     * SK + k0 + 2 * t]);
            a[mi][1] = *reinterpret_cast<const unsigned*>(&sH[(R + g + 8) * SK + k0 + 2 * t]);
            a[mi][2] = *reinterpret_cast<const unsigned*>(&sH[(R + g)     * SK + k0 + 2 * t + 8]);
            a[mi][3] = *reinterpret_cast<const unsigned*>(&sH[(R + g + 8) * SK + k0 + 2 * t + 8]);
        }
        #pragma unroll
        for (int ni = 0; ni < 8; ni++) {
            int C = warpN * 64 + ni * 8;
            unsigned b[2];
            b[0] = *reinterpret_cast<const unsigned*>(&sWt[(C + g) * SK + k0 + 2 * t]);
            b[1] = *reinterpret_cast<const unsigned*>(&sWt[(C + g) * SK + k0 + 2 * t + 8]);
            mma_f16(acc[0][ni], a[0], b);
            mma_f16(acc[1][ni], a[1], b);
        }
    }

    float nmA[2] = {1.f, 1.f}, nmB[2] = {1.f, 1.f};
    if (LAYER1) {
        #pragma unroll
        for (int mi = 0; mi < 2; mi++) {
            int r1 = row0 + warpM * 32 + mi * 16 + g;
            int r2 = r1 + 8;
            nmA[mi] = (r1 < N_NODES) ? g_norm[r1] : 0.f;
            nmB[mi] = (r2 < N_NODES) ? g_norm[r2] : 0.f;
        }
    }

    #pragma unroll
    for (int ni = 0; ni < 8; ni++) {
        int c = warpN * 64 + ni * 8 + 2 * t;
        float2 bb = *reinterpret_cast<const float2*>(&bias[c]);
        #pragma unroll
        for (int mi = 0; mi < 2; mi++) {
            int r1 = row0 + warpM * 32 + mi * 16 + g;
            int r2 = r1 + 8;
            float2 o1 = make_float2(acc[mi][ni][0] + bb.x,
                                    acc[mi][ni][1] + bb.y);
            float2 o2 = make_float2(acc[mi][ni][2] + bb.x,
                                    acc[mi][ni][3] + bb.y);
            if (LAYER1) {
                o1.x = fmaxf(o1.x, 0.f) * nmA[mi];
                o1.y = fmaxf(o1.y, 0.f) * nmA[mi];
                o2.x = fmaxf(o2.x, 0.f) * nmB[mi];
                o2.y = fmaxf(o2.y, 0.f) * nmB[mi];
                if (r1 < N_NODES)
                    *reinterpret_cast<half2*>(&g_h1[r1 * D + c]) =
                        __floats2half2_rn(o1.x, o1.y);
                if (r2 < N_NODES)
                    *reinterpret_cast<half2*>(&g_h1[r2 * D + c]) =
                        __floats2half2_rn(o2.x, o2.y);
            } else {
                if (r1 < N_NODES)
                    *reinterpret_cast<float2*>(&outp[r1 * D + c]) = o1;
                if (r2 < N_NODES)
                    *reinterpret_cast<float2*>(&outp[r2 * D + c]) = o2;
            }
        }
    }
}

// ---------------------------------------------------------------------------
// Launch
// ---------------------------------------------------------------------------
extern "C" void kernel_launch(void* const* d_in, const int* in_sizes, int n_in,
                              void* d_out, int out_size) {
    const float* features = (const float*)d_in[0];
    const int*   src      = (const int*)d_in[1];
    const int*   dst      = (const int*)d_in[2];
    const float* W0       = (const float*)d_in[3];
    const float* b0       = (const float*)d_in[4];
    const float* W1       = (const float*)d_in[5];
    const float* b1       = (const float*)d_in[6];
    float* out = (float*)d_out;

    const int SMEM_EPI = 2 * D * SK * sizeof(__half);  // 69632 B
    cudaFuncSetAttribute(epilogue_kernel<true>,
                         cudaFuncAttributeMaxDynamicSharedMemorySize, SMEM_EPI);
    cudaFuncSetAttribute(epilogue_kernel<false>,
                         cudaFuncAttributeMaxDynamicSharedMemorySize, SMEM_EPI);

    const int edge4Blocks = (N_EDGES / 4 + 255) / 256;
    const int aggBlocks   = (N_NODES + 7) / 8;
    const int epiBlocks   = (N_NODES + 127) / 128;

    // CSR build + prescale (3 launches)
    hist_kernel<<<edge4Blocks, 256>>>((const int4*)dst);
    scan_kernel<<<NB, SCAN_BLK>>>();
    fill_prescale_kernel<<<FILL_BLOCKS + PRE_BLOCKS, 256>>>(
        (const int2*)src, (const int2*)dst, (const float4*)features);

    // Layer 1
    aggregate_kernel<true><<<aggBlocks, 256>>>();
    epilogue_kernel<true><<<epiBlocks, 256, SMEM_EPI>>>(W0, b0, nullptr);

    // Layer 2 (epilogue also resets deg/counter for the next replay)
    aggregate_kernel<false><<<aggBlocks, 256>>>();
    epilogue_kernel<false><<<epiBlocks, 256, SMEM_EPI>>>(W1, b1, out);
}